// round 1
// baseline (speedup 1.0000x reference)
#include <cuda_runtime.h>
#include <math.h>

// Problem constants
#define SDIM 4096      // spatial = 64*64
#define CDIM 256       // channels
#define EDIM 128       // embed
#define NBATCH 4

// Scratch (device-global: allocation-free per harness rules)
__device__ float g_tp[(size_t)NBATCH * SDIM * (2 * EDIM)];  // [n][s][0:128]=theta, [128:256]=phi
__device__ float g_f [(size_t)NBATCH * SDIM * SDIM];        // [n][s][t] attention logits/probs
__device__ float g_y [(size_t)NBATCH * SDIM * CDIM];        // [n][s][c]

// ---------------------------------------------------------------------------
// Generic NT GEMM: C[M,N] = alpha * A[M,K] * B[N,K]^T (+ optional add term)
//   A: if !ATRANS, row-major [M,K] with leading dim lda (contiguous along k)
//      if  ATRANS, element A[m,k] lives at A[k*lda + m] (contiguous along m)
//   B: row-major [N,K], leading dim ldb (contiguous along k)
//   C: row-major [M,N], leading dim ldc
// Tiles: 128x128x8, 256 threads, 8x8 per thread (split 4+4 layout).
// All problem dims here are exact multiples of the tiles -> no bounds checks.
// ---------------------------------------------------------------------------
template<bool ATRANS, bool ADD>
__global__ __launch_bounds__(256) void gemm_nt(
    const float* __restrict__ A, long lda, long strideA,
    const float* __restrict__ B, long ldb, long strideB,
    float* __restrict__ Cp, long ldc, long strideC,
    const float* __restrict__ Cadd, long strideAdd,
    int M, int N, int K, float alpha)
{
    const int bz = blockIdx.z;
    A  += (size_t)bz * strideA;
    B  += (size_t)bz * strideB;
    Cp += (size_t)bz * strideC;
    if (ADD) Cadd += (size_t)bz * strideAdd;

    __shared__ float As[8][128];
    __shared__ float Bs[8][128];

    const int tid = threadIdx.x;
    const int tx = tid & 15;        // n-direction thread coord
    const int ty = tid >> 4;        // m-direction thread coord
    const int m0 = blockIdx.y * 128;
    const int n0 = blockIdx.x * 128;

    // loader coords
    const int lrow = tid >> 1;              // 0..127  (tile row for non-trans loads)
    const int lkq  = (tid & 1) * 4;         // k quad
    const int tk   = tid >> 5;              // 0..7    (k row for trans-A load)
    const int tm4  = (tid & 31) * 4;        // m offset for trans-A load

    float acc[8][8];
    #pragma unroll
    for (int i = 0; i < 8; i++)
        #pragma unroll
        for (int j = 0; j < 8; j++) acc[i][j] = 0.0f;

    for (int k0 = 0; k0 < K; k0 += 8) {
        if (ATRANS) {
            // contiguous along m -> coalesced float4, direct (k-major) smem store
            const float4 v = *reinterpret_cast<const float4*>(
                &A[(size_t)(k0 + tk) * lda + m0 + tm4]);
            *reinterpret_cast<float4*>(&As[tk][tm4]) = v;
        } else {
            const float4 v = *reinterpret_cast<const float4*>(
                &A[(size_t)(m0 + lrow) * lda + k0 + lkq]);
            As[lkq + 0][lrow] = v.x; As[lkq + 1][lrow] = v.y;
            As[lkq + 2][lrow] = v.z; As[lkq + 3][lrow] = v.w;
        }
        {
            const float4 v = *reinterpret_cast<const float4*>(
                &B[(size_t)(n0 + lrow) * ldb + k0 + lkq]);
            Bs[lkq + 0][lrow] = v.x; Bs[lkq + 1][lrow] = v.y;
            Bs[lkq + 2][lrow] = v.z; Bs[lkq + 3][lrow] = v.w;
        }
        __syncthreads();

        #pragma unroll
        for (int k = 0; k < 8; k++) {
            float4 a0 = *reinterpret_cast<const float4*>(&As[k][ty * 4]);
            float4 a1 = *reinterpret_cast<const float4*>(&As[k][64 + ty * 4]);
            float4 b0 = *reinterpret_cast<const float4*>(&Bs[k][tx * 4]);
            float4 b1 = *reinterpret_cast<const float4*>(&Bs[k][64 + tx * 4]);
            float a[8] = {a0.x, a0.y, a0.z, a0.w, a1.x, a1.y, a1.z, a1.w};
            float b[8] = {b0.x, b0.y, b0.z, b0.w, b1.x, b1.y, b1.z, b1.w};
            #pragma unroll
            for (int i = 0; i < 8; i++)
                #pragma unroll
                for (int j = 0; j < 8; j++)
                    acc[i][j] += a[i] * b[j];
        }
        __syncthreads();
    }

    // epilogue: rows {ty*4+0..3, 64+ty*4+0..3}, cols {tx*4+0..3, 64+tx*4+0..3}
    #pragma unroll
    for (int i = 0; i < 8; i++) {
        const int m = m0 + ((i < 4) ? (ty * 4 + i) : (64 + ty * 4 + (i - 4)));
        #pragma unroll
        for (int j = 0; j < 8; j++) {
            const int n = n0 + ((j < 4) ? (tx * 4 + j) : (64 + tx * 4 + (j - 4)));
            float v = acc[i][j] * alpha;
            if (ADD) v += Cadd[(size_t)m * ldc + n];
            Cp[(size_t)m * ldc + n] = v;
        }
    }
}

// ---------------------------------------------------------------------------
// Row softmax over g_f: one block per row of 4096 fp32.
// ---------------------------------------------------------------------------
__global__ __launch_bounds__(256) void softmax_rows(float* __restrict__ f)
{
    const size_t row = blockIdx.x;
    float4* p4 = reinterpret_cast<float4*>(f + row * (size_t)SDIM);
    const int tid = threadIdx.x;
    const int lane = tid & 31, wid = tid >> 5;

    float4 v[4];
    float mx = -1e30f;
    #pragma unroll
    for (int i = 0; i < 4; i++) {
        v[i] = p4[tid + i * 256];
        mx = fmaxf(mx, fmaxf(fmaxf(v[i].x, v[i].y), fmaxf(v[i].z, v[i].w)));
    }

    __shared__ float sred[8];
    #pragma unroll
    for (int o = 16; o > 0; o >>= 1) mx = fmaxf(mx, __shfl_xor_sync(0xffffffffu, mx, o));
    if (lane == 0) sred[wid] = mx;
    __syncthreads();
    float bm = sred[0];
    #pragma unroll
    for (int i = 1; i < 8; i++) bm = fmaxf(bm, sred[i]);
    __syncthreads();

    float s = 0.0f;
    #pragma unroll
    for (int i = 0; i < 4; i++) {
        v[i].x = expf(v[i].x - bm); v[i].y = expf(v[i].y - bm);
        v[i].z = expf(v[i].z - bm); v[i].w = expf(v[i].w - bm);
        s += v[i].x + v[i].y + v[i].z + v[i].w;
    }
    #pragma unroll
    for (int o = 16; o > 0; o >>= 1) s += __shfl_xor_sync(0xffffffffu, s, o);
    if (lane == 0) sred[wid] = s;
    __syncthreads();
    float bs = 0.0f;
    #pragma unroll
    for (int i = 0; i < 8; i++) bs += sred[i];
    const float inv = 1.0f / bs;

    #pragma unroll
    for (int i = 0; i < 4; i++) {
        v[i].x *= inv; v[i].y *= inv; v[i].z *= inv; v[i].w *= inv;
        p4[tid + i * 256] = v[i];
    }
}

// ---------------------------------------------------------------------------
extern "C" void kernel_launch(void* const* d_in, const int* in_sizes, int n_in,
                              void* d_out, int out_size)
{
    const float* x       = (const float*)d_in[0];  // [4,256,64,64]
    const float* theta_w = (const float*)d_in[1];  // [128,256]
    const float* phi_w   = (const float*)d_in[2];  // [128,256]
    const float* proj_w  = (const float*)d_in[3];  // [256,256]
    float* out = (float*)d_out;

    float *tp, *f, *y;
    cudaGetSymbolAddress((void**)&tp, g_tp);
    cudaGetSymbolAddress((void**)&f,  g_f);
    cudaGetSymbolAddress((void**)&y,  g_y);

    const long xBatch  = (long)CDIM * SDIM;     // 1,048,576
    const long tpBatch = (long)SDIM * 2 * EDIM; // 1,048,576
    const long fBatch  = (long)SDIM * SDIM;     // 16,777,216
    const long yBatch  = (long)SDIM * CDIM;     // 1,048,576

    // op1a: theta[n][s][e] = sum_c theta_w[e,c] * x[n,c,s]
    //   A = x (trans: A[s,c] at x[c*S + s]), B = theta_w [E,C], C = tp[..,0:128]
    gemm_nt<true, false><<<dim3(1, 32, 4), 256>>>(
        x, SDIM, xBatch,
        theta_w, CDIM, 0,
        tp, 2 * EDIM, tpBatch,
        nullptr, 0,
        SDIM, EDIM, CDIM, 1.0f);

    // op1b: phi -> tp[..,128:256]
    gemm_nt<true, false><<<dim3(1, 32, 4), 256>>>(
        x, SDIM, xBatch,
        phi_w, CDIM, 0,
        tp + EDIM, 2 * EDIM, tpBatch,
        nullptr, 0,
        SDIM, EDIM, CDIM, 1.0f);

    // op2: f[n][s][t] = (1/sqrt(E)) * sum_e theta[s,e] * phi[t,e]
    const float alpha = 1.0f / sqrtf((float)EDIM);
    gemm_nt<false, false><<<dim3(32, 32, 4), 256>>>(
        tp, 2 * EDIM, tpBatch,
        tp + EDIM, 2 * EDIM, tpBatch,
        f, SDIM, fBatch,
        nullptr, 0,
        SDIM, SDIM, EDIM, alpha);

    // op3: softmax over t for each (n, s)
    softmax_rows<<<NBATCH * SDIM, 256>>>(f);

    // op4: y[n][s][c] = sum_t f[s,t] * x[n,c,t]
    //   A = f [S,S], B = x [C,S] (rows are c, contiguous along t)
    gemm_nt<false, false><<<dim3(2, 32, 4), 256>>>(
        f, SDIM, fBatch,
        x, SDIM, xBatch,
        y, CDIM, yBatch,
        nullptr, 0,
        SDIM, CDIM, SDIM, 1.0f);

    // op5: out[n][o][s] = x[n][o][s] + sum_c proj_w[o,c] * y[n][s][c]
    //   A = proj_w [C,C], B = y [S,C], C = out [C,S] with add = x
    gemm_nt<false, true><<<dim3(32, 2, 4), 256>>>(
        proj_w, CDIM, 0,
        y, CDIM, yBatch,
        out, SDIM, (long)CDIM * SDIM,
        x, xBatch,
        CDIM, SDIM, CDIM, 1.0f);
}

// round 3
// speedup vs baseline: 4.4974x; 4.4974x over previous
#include <cuda_runtime.h>
#include <cuda_bf16.h>
#include <math.h>
#include <cstdint>

#define SDIM 4096
#define CDIM 256
#define EDIM 128
#define NBATCH 4

// ---- scratch (device globals: allocation-free) ----
__device__ __nv_bfloat16 g_tp[(size_t)NBATCH * SDIM * (2 * EDIM)]; // [n][s][0:128)=theta [128:256)=phi
__device__ __nv_bfloat16 g_f [(size_t)NBATCH * SDIM * SDIM];       // unnormalized exp(logits)
__device__ __nv_bfloat16 g_xb[(size_t)NBATCH * CDIM * SDIM];       // x in bf16 [n][c][s]
__device__ float         g_y [(size_t)NBATCH * SDIM * CDIM];       // [n][s][c] fp32
__device__ float         g_Z [(size_t)NBATCH * SDIM];              // row sums

// ============================ low-level helpers ============================
__device__ __forceinline__ uint32_t smem_u32(const void* p) {
    uint32_t a;
    asm("{ .reg .u64 t; cvta.to.shared.u64 t, %1; cvt.u32.u64 %0, t; }" : "=r"(a) : "l"(p));
    return a;
}
__device__ __forceinline__ void ldsm4(uint32_t r[4], uint32_t addr) {
    asm volatile("ldmatrix.sync.aligned.m8n8.x4.shared.b16 {%0,%1,%2,%3}, [%4];"
                 : "=r"(r[0]), "=r"(r[1]), "=r"(r[2]), "=r"(r[3]) : "r"(addr));
}
__device__ __forceinline__ void mma16816(float c[4], const uint32_t a[4], uint32_t b0, uint32_t b1) {
    asm volatile("mma.sync.aligned.m16n8k16.row.col.f32.bf16.bf16.f32 "
                 "{%0,%1,%2,%3},{%4,%5,%6,%7},{%8,%9},{%0,%1,%2,%3};"
                 : "+f"(c[0]), "+f"(c[1]), "+f"(c[2]), "+f"(c[3])
                 : "r"(a[0]), "r"(a[1]), "r"(a[2]), "r"(a[3]), "r"(b0), "r"(b1));
}
__device__ __forceinline__ void cp16(uint32_t saddr, const void* g) {
    asm volatile("cp.async.cg.shared.global [%0], [%1], 16;" :: "r"(saddr), "l"(g));
}
#define CP_COMMIT() asm volatile("cp.async.commit_group;" ::: "memory")

// Load one 128-row x 64-col bf16 tile (128B rows) gmem->smem with XOR-128B swizzle.
// 256 threads, 4 x 16B each. ldg = row stride in elements.
__device__ __forceinline__ void load_tile_async(uint32_t sdst, const __nv_bfloat16* g, int ldg) {
    const int tid = threadIdx.x;
    #pragma unroll
    for (int i = 0; i < 4; i++) {
        const int c = tid + i * 256;          // 0..1023
        const int r = c >> 3, kc = c & 7;     // row, 16B-chunk
        const uint32_t so = sdst + r * 128 + (((uint32_t)kc * 16) ^ ((r & 7) * 16));
        cp16(so, g + (size_t)r * ldg + kc * 8);
    }
}

// Compute one BK=64 chunk: acc[4][4][4] += A(128x64) * B(128x64)^T for this warp.
// wm in {0,1} (m group of 64), wn in {0..3} (n group of 32).
__device__ __forceinline__ void compute_chunk(uint32_t sA, uint32_t sB,
                                              int wm, int wn, int lane,
                                              float acc[4][4][4]) {
    #pragma unroll
    for (int ks = 0; ks < 4; ks++) {
        const int kc = ks * 2 + (lane >> 4);  // 16B chunk within row
        uint32_t a[4][4];
        #pragma unroll
        for (int mi = 0; mi < 4; mi++) {
            const int row = wm * 64 + mi * 16 + (lane & 15);
            const uint32_t addr = sA + row * 128 + (((uint32_t)kc * 16) ^ ((row & 7) * 16));
            ldsm4(a[mi], addr);
        }
        uint32_t b[4][2];
        #pragma unroll
        for (int nh = 0; nh < 2; nh++) {
            const int row = wn * 32 + nh * 16 + (lane & 15);
            const uint32_t addr = sB + row * 128 + (((uint32_t)kc * 16) ^ ((row & 7) * 16));
            uint32_t r4[4]; ldsm4(r4, addr);
            b[nh * 2 + 0][0] = r4[0]; b[nh * 2 + 0][1] = r4[2];
            b[nh * 2 + 1][0] = r4[1]; b[nh * 2 + 1][1] = r4[3];
        }
        #pragma unroll
        for (int mi = 0; mi < 4; mi++)
            #pragma unroll
            for (int ni = 0; ni < 4; ni++)
                mma16816(acc[mi][ni], a[mi], b[ni][0], b[ni][1]);
    }
}

// smem buffers (dynamic, 64KB): A0 @0, B0 @16K, A1 @32K, B1 @48K
#define SM_A(st) ((uint32_t)((st) ? 32768 : 0))
#define SM_B(st) ((uint32_t)((st) ? 49152 : 16384))

// ============================ x -> bf16 (+ zero Z) ============================
__global__ __launch_bounds__(256) void conv_x_bf16(const float4* __restrict__ x,
                                                   uint2* __restrict__ xb,
                                                   float* __restrict__ Z, int n4)
{
    const int gt = blockIdx.x * blockDim.x + threadIdx.x;
    if (gt < NBATCH * SDIM) Z[gt] = 0.0f;
    for (int i = gt; i < n4; i += gridDim.x * blockDim.x) {
        float4 v = x[i];
        __nv_bfloat162 a = __floats2bfloat162_rn(v.x, v.y);
        __nv_bfloat162 b = __floats2bfloat162_rn(v.z, v.w);
        xb[i] = make_uint2(*reinterpret_cast<uint32_t*>(&a), *reinterpret_cast<uint32_t*>(&b));
    }
}

// ============================ SIMT GEMM (small ops, from R1) ============================
template<bool ATRANS, bool ADD, bool OUTBF16>
__global__ __launch_bounds__(256) void gemm_nt(
    const float* __restrict__ A, long lda, long strideA,
    const float* __restrict__ B, long ldb, long strideB,
    void* __restrict__ Cp_, long ldc, long strideC,
    const float* __restrict__ Cadd, long strideAdd,
    int M, int N, int K, float alpha)
{
    const int bz = blockIdx.z;
    A += (size_t)bz * strideA;
    B += (size_t)bz * strideB;
    if (ADD) Cadd += (size_t)bz * strideAdd;

    __shared__ float As[8][128];
    __shared__ float Bs[8][128];

    const int tid = threadIdx.x;
    const int tx = tid & 15, ty = tid >> 4;
    const int m0 = blockIdx.y * 128, n0 = blockIdx.x * 128;
    const int lrow = tid >> 1, lkq = (tid & 1) * 4;
    const int tk = tid >> 5, tm4 = (tid & 31) * 4;

    float acc[8][8];
    #pragma unroll
    for (int i = 0; i < 8; i++)
        #pragma unroll
        for (int j = 0; j < 8; j++) acc[i][j] = 0.0f;

    for (int k0 = 0; k0 < K; k0 += 8) {
        if (ATRANS) {
            const float4 v = *reinterpret_cast<const float4*>(&A[(size_t)(k0 + tk) * lda + m0 + tm4]);
            *reinterpret_cast<float4*>(&As[tk][tm4]) = v;
        } else {
            const float4 v = *reinterpret_cast<const float4*>(&A[(size_t)(m0 + lrow) * lda + k0 + lkq]);
            As[lkq + 0][lrow] = v.x; As[lkq + 1][lrow] = v.y;
            As[lkq + 2][lrow] = v.z; As[lkq + 3][lrow] = v.w;
        }
        {
            const float4 v = *reinterpret_cast<const float4*>(&B[(size_t)(n0 + lrow) * ldb + k0 + lkq]);
            Bs[lkq + 0][lrow] = v.x; Bs[lkq + 1][lrow] = v.y;
            Bs[lkq + 2][lrow] = v.z; Bs[lkq + 3][lrow] = v.w;
        }
        __syncthreads();
        #pragma unroll
        for (int k = 0; k < 8; k++) {
            float4 a0 = *reinterpret_cast<const float4*>(&As[k][ty * 4]);
            float4 a1 = *reinterpret_cast<const float4*>(&As[k][64 + ty * 4]);
            float4 b0 = *reinterpret_cast<const float4*>(&Bs[k][tx * 4]);
            float4 b1 = *reinterpret_cast<const float4*>(&Bs[k][64 + tx * 4]);
            float a[8] = {a0.x, a0.y, a0.z, a0.w, a1.x, a1.y, a1.z, a1.w};
            float b[8] = {b0.x, b0.y, b0.z, b0.w, b1.x, b1.y, b1.z, b1.w};
            #pragma unroll
            for (int i = 0; i < 8; i++)
                #pragma unroll
                for (int j = 0; j < 8; j++)
                    acc[i][j] += a[i] * b[j];
        }
        __syncthreads();
    }

    #pragma unroll
    for (int i = 0; i < 8; i++) {
        const int m = m0 + ((i < 4) ? (ty * 4 + i) : (64 + ty * 4 + (i - 4)));
        #pragma unroll
        for (int j = 0; j < 8; j++) {
            const int n = n0 + ((j < 4) ? (tx * 4 + j) : (64 + tx * 4 + (j - 4)));
            float v = acc[i][j] * alpha;
            if (ADD) v += Cadd[(size_t)m * ldc + n];
            if (OUTBF16) {
                __nv_bfloat16* C = (__nv_bfloat16*)Cp_ + (size_t)bz * strideC;
                C[(size_t)m * ldc + n] = __float2bfloat16(v);
            } else {
                float* C = (float*)Cp_ + (size_t)bz * strideC;
                C[(size_t)m * ldc + n] = v;
            }
        }
    }
}

// ============================ fused logits + exp (HMMA) ============================
// f[n][s][t] = exp(alpha * theta[s,:] . phi[t,:]) (bf16, unnormalized), Z[n][s] += rowsum.
// grid (32 n-tiles, 32 m-tiles, 4 batches), 256 threads, K = 128 (2 chunks).
__global__ __launch_bounds__(256)
void logits_exp_hmma(const __nv_bfloat16* __restrict__ tp,
                     __nv_bfloat16* __restrict__ f,
                     float* __restrict__ Z)
{
    extern __shared__ char smem[];
    const uint32_t sb = smem_u32(smem);
    const int tid = threadIdx.x, lane = tid & 31, wid = tid >> 5;
    const int wm = wid & 1, wn = wid >> 1;
    const int z = blockIdx.z, m0 = blockIdx.y * 128, n0 = blockIdx.x * 128;

    const __nv_bfloat16* Abase = tp + ((size_t)(z * SDIM + m0)) * 256;        // theta
    const __nv_bfloat16* Bbase = tp + ((size_t)(z * SDIM + n0)) * 256 + 128;  // phi

    float acc[4][4][4];
    #pragma unroll
    for (int a = 0; a < 4; a++)
        #pragma unroll
        for (int b = 0; b < 4; b++)
            #pragma unroll
            for (int c = 0; c < 4; c++) acc[a][b][c] = 0.0f;

    load_tile_async(sb + SM_A(0), Abase, 256);
    load_tile_async(sb + SM_B(0), Bbase, 256);
    CP_COMMIT();

    #pragma unroll
    for (int kt = 0; kt < 2; kt++) {
        if (kt + 1 < 2) {
            load_tile_async(sb + SM_A(1), Abase + 64, 256);
            load_tile_async(sb + SM_B(1), Bbase + 64, 256);
            CP_COMMIT();
            asm volatile("cp.async.wait_group 1;" ::: "memory");
        } else {
            asm volatile("cp.async.wait_group 0;" ::: "memory");
        }
        __syncthreads();
        compute_chunk(sb + SM_A(kt & 1), sb + SM_B(kt & 1), wm, wn, lane, acc);
        __syncthreads();
    }

    // epilogue: exp + bf16 store + row-sum atomics
    const float alpha = 0.08838834764831845f; // 1/sqrt(128)
    const int lrow = lane >> 2, lcol2 = (lane & 3) * 2;
    #pragma unroll
    for (int mi = 0; mi < 4; mi++) {
        const int gr0 = m0 + wm * 64 + mi * 16 + lrow;
        const int gr1 = gr0 + 8;
        float rs0 = 0.0f, rs1 = 0.0f;
        #pragma unroll
        for (int ni = 0; ni < 4; ni++) {
            const int col = n0 + wn * 32 + ni * 8 + lcol2;
            float e00 = __expf(acc[mi][ni][0] * alpha);
            float e01 = __expf(acc[mi][ni][1] * alpha);
            float e10 = __expf(acc[mi][ni][2] * alpha);
            float e11 = __expf(acc[mi][ni][3] * alpha);
            rs0 += e00 + e01; rs1 += e10 + e11;
            __nv_bfloat162 h0 = __floats2bfloat162_rn(e00, e01);
            __nv_bfloat162 h1 = __floats2bfloat162_rn(e10, e11);
            *reinterpret_cast<uint32_t*>(f + ((size_t)z * SDIM + gr0) * SDIM + col) =
                *reinterpret_cast<uint32_t*>(&h0);
            *reinterpret_cast<uint32_t*>(f + ((size_t)z * SDIM + gr1) * SDIM + col) =
                *reinterpret_cast<uint32_t*>(&h1);
        }
        rs0 += __shfl_xor_sync(0xffffffffu, rs0, 1);
        rs0 += __shfl_xor_sync(0xffffffffu, rs0, 2);
        rs1 += __shfl_xor_sync(0xffffffffu, rs1, 1);
        rs1 += __shfl_xor_sync(0xffffffffu, rs1, 2);
        if ((lane & 3) == 0) {
            atomicAdd(&Z[(size_t)z * SDIM + gr0], rs0);
            atomicAdd(&Z[(size_t)z * SDIM + gr1], rs1);
        }
    }
}

// ============================ attend (HMMA): y = (f @ x^T) / Z ============================
// y[n][s][c] = (1/Z[s]) * sum_t f[s,t] * xb[c,t].
// grid (2 n-tiles, 32 m-tiles, 4 batches), 256 threads, K = 4096 (64 chunks).
__global__ __launch_bounds__(256)
void attend_hmma(const __nv_bfloat16* __restrict__ f,
                 const __nv_bfloat16* __restrict__ xb,
                 const float* __restrict__ Z,
                 float* __restrict__ y)
{
    extern __shared__ char smem[];
    const uint32_t sb = smem_u32(smem);
    const int tid = threadIdx.x, lane = tid & 31, wid = tid >> 5;
    const int wm = wid & 1, wn = wid >> 1;
    const int z = blockIdx.z, m0 = blockIdx.y * 128, n0 = blockIdx.x * 128;

    const __nv_bfloat16* Abase = f + ((size_t)z * SDIM + m0) * SDIM;   // lda 4096
    const __nv_bfloat16* Bbase = xb + ((size_t)z * CDIM + n0) * SDIM;  // ldb 4096

    float acc[4][4][4];
    #pragma unroll
    for (int a = 0; a < 4; a++)
        #pragma unroll
        for (int b = 0; b < 4; b++)
            #pragma unroll
            for (int c = 0; c < 4; c++) acc[a][b][c] = 0.0f;

    load_tile_async(sb + SM_A(0), Abase, SDIM);
    load_tile_async(sb + SM_B(0), Bbase, SDIM);
    CP_COMMIT();

    const int KT = SDIM / 64; // 64
    for (int kt = 0; kt < KT; kt++) {
        if (kt + 1 < KT) {
            load_tile_async(sb + SM_A((kt + 1) & 1), Abase + (kt + 1) * 64, SDIM);
            load_tile_async(sb + SM_B((kt + 1) & 1), Bbase + (kt + 1) * 64, SDIM);
            CP_COMMIT();
            asm volatile("cp.async.wait_group 1;" ::: "memory");
        } else {
            asm volatile("cp.async.wait_group 0;" ::: "memory");
        }
        __syncthreads();
        compute_chunk(sb + SM_A(kt & 1), sb + SM_B(kt & 1), wm, wn, lane, acc);
        __syncthreads();
    }

    // epilogue: scale by 1/Z and store fp32 y (row-major, ldc = 256)
    const int lrow = lane >> 2, lcol2 = (lane & 3) * 2;
    #pragma unroll
    for (int mi = 0; mi < 4; mi++) {
        const int gr0 = m0 + wm * 64 + mi * 16 + lrow;
        const int gr1 = gr0 + 8;
        const float iz0 = 1.0f / Z[(size_t)z * SDIM + gr0];
        const float iz1 = 1.0f / Z[(size_t)z * SDIM + gr1];
        #pragma unroll
        for (int ni = 0; ni < 4; ni++) {
            const int col = n0 + wn * 32 + ni * 8 + lcol2;
            float2 v0 = make_float2(acc[mi][ni][0] * iz0, acc[mi][ni][1] * iz0);
            float2 v1 = make_float2(acc[mi][ni][2] * iz1, acc[mi][ni][3] * iz1);
            *reinterpret_cast<float2*>(y + ((size_t)z * SDIM + gr0) * CDIM + col) = v0;
            *reinterpret_cast<float2*>(y + ((size_t)z * SDIM + gr1) * CDIM + col) = v1;
        }
    }
}

// ============================ launch ============================
extern "C" void kernel_launch(void* const* d_in, const int* in_sizes, int n_in,
                              void* d_out, int out_size)
{
    const float* x       = (const float*)d_in[0];
    const float* theta_w = (const float*)d_in[1];
    const float* phi_w   = (const float*)d_in[2];
    const float* proj_w  = (const float*)d_in[3];
    float* out = (float*)d_out;

    __nv_bfloat16 *tp, *f, *xb;
    float *y, *Z;
    cudaGetSymbolAddress((void**)&tp, g_tp);
    cudaGetSymbolAddress((void**)&f,  g_f);
    cudaGetSymbolAddress((void**)&xb, g_xb);
    cudaGetSymbolAddress((void**)&y,  g_y);
    cudaGetSymbolAddress((void**)&Z,  g_Z);

    cudaFuncSetAttribute(logits_exp_hmma, cudaFuncAttributeMaxDynamicSharedMemorySize, 65536);
    cudaFuncSetAttribute(attend_hmma,     cudaFuncAttributeMaxDynamicSharedMemorySize, 65536);

    const long xBatch  = (long)CDIM * SDIM;
    const long tpBatch = (long)SDIM * 2 * EDIM;

    // 0: x -> bf16 (+ zero Z)
    conv_x_bf16<<<1024, 256>>>((const float4*)x, (uint2*)xb, Z,
                               (int)((size_t)NBATCH * CDIM * SDIM / 4));

    // 1: theta / phi projections (SIMT, fp32 in -> bf16 out)
    gemm_nt<true, false, true><<<dim3(1, 32, 4), 256>>>(
        x, SDIM, xBatch, theta_w, CDIM, 0,
        tp, 2 * EDIM, tpBatch, nullptr, 0,
        SDIM, EDIM, CDIM, 1.0f);
    gemm_nt<true, false, true><<<dim3(1, 32, 4), 256>>>(
        x, SDIM, xBatch, phi_w, CDIM, 0,
        tp + EDIM, 2 * EDIM, tpBatch, nullptr, 0,
        SDIM, EDIM, CDIM, 1.0f);

    // 2: fused logits -> exp + row sums  [HMMA]
    logits_exp_hmma<<<dim3(32, 32, 4), 256, 65536>>>(tp, f, Z);

    // 3: attend + 1/Z  [HMMA]
    attend_hmma<<<dim3(2, 32, 4), 256, 65536>>>(f, xb, Z, y);

    // 4: output projection + residual (SIMT fp32)
    gemm_nt<false, true, false><<<dim3(32, 2, 4), 256>>>(
        proj_w, CDIM, 0, y, CDIM, (long)SDIM * CDIM,
        out, SDIM, (long)CDIM * SDIM, x, xBatch,
        CDIM, SDIM, CDIM, 1.0f);
}

// round 4
// speedup vs baseline: 6.7423x; 1.4992x over previous
#include <cuda_runtime.h>
#include <cuda_bf16.h>
#include <math.h>
#include <cstdint>

#define SDIM 4096
#define CDIM 256
#define EDIM 128
#define NBATCH 4

// ---- scratch (device globals: allocation-free) ----
__device__ __nv_bfloat16 g_tp[(size_t)NBATCH * SDIM * (2 * EDIM)]; // [n][s][0:128)=theta [128:256)=phi
__device__ __nv_bfloat16 g_f [(size_t)NBATCH * SDIM * SDIM];       // unnormalized exp(logits)
__device__ __nv_bfloat16 g_xb[(size_t)NBATCH * CDIM * SDIM];       // x bf16 [n][c][s]
__device__ __nv_bfloat16 g_yb[(size_t)NBATCH * SDIM * CDIM];       // y bf16 [n][s][c]
__device__ __nv_bfloat16 g_w2[256 * 256];                          // [o][c]: rows 0-127 theta_w, 128-255 phi_w
__device__ __nv_bfloat16 g_w3[256 * 256];                          // proj_w bf16 [o][c]
__device__ float         g_Z [(size_t)NBATCH * SDIM];              // row sums

// ============================ low-level helpers ============================
__device__ __forceinline__ uint32_t smem_u32(const void* p) {
    uint32_t a;
    asm("{ .reg .u64 t; cvta.to.shared.u64 t, %1; cvt.u32.u64 %0, t; }" : "=r"(a) : "l"(p));
    return a;
}
__device__ __forceinline__ void ldsm4(uint32_t r[4], uint32_t addr) {
    asm volatile("ldmatrix.sync.aligned.m8n8.x4.shared.b16 {%0,%1,%2,%3}, [%4];"
                 : "=r"(r[0]), "=r"(r[1]), "=r"(r[2]), "=r"(r[3]) : "r"(addr));
}
__device__ __forceinline__ void ldsm4t(uint32_t r[4], uint32_t addr) {
    asm volatile("ldmatrix.sync.aligned.m8n8.x4.trans.shared.b16 {%0,%1,%2,%3}, [%4];"
                 : "=r"(r[0]), "=r"(r[1]), "=r"(r[2]), "=r"(r[3]) : "r"(addr));
}
__device__ __forceinline__ void mma16816(float c[4], const uint32_t a[4], uint32_t b0, uint32_t b1) {
    asm volatile("mma.sync.aligned.m16n8k16.row.col.f32.bf16.bf16.f32 "
                 "{%0,%1,%2,%3},{%4,%5,%6,%7},{%8,%9},{%0,%1,%2,%3};"
                 : "+f"(c[0]), "+f"(c[1]), "+f"(c[2]), "+f"(c[3])
                 : "r"(a[0]), "r"(a[1]), "r"(a[2]), "r"(a[3]), "r"(b0), "r"(b1));
}
__device__ __forceinline__ void cp16(uint32_t saddr, const void* g) {
    asm volatile("cp.async.cg.shared.global [%0], [%1], 16;" :: "r"(saddr), "l"(g));
}
#define CP_COMMIT() asm volatile("cp.async.commit_group;" ::: "memory")
#define CP_WAIT(N)  asm volatile("cp.async.wait_group %0;" :: "n"(N) : "memory")

// 128 rows x 64 cols bf16 (128B rows), XOR-16B swizzle keyed on row&7.
__device__ __forceinline__ void load_tile_128x64(uint32_t sdst, const __nv_bfloat16* g, int ldg) {
    const int tid = threadIdx.x;
    #pragma unroll
    for (int i = 0; i < 4; i++) {
        const int c = tid + i * 256;
        const int r = c >> 3, kc = c & 7;
        const uint32_t so = sdst + r * 128 + (((uint32_t)kc * 16) ^ ((r & 7) * 16));
        cp16(so, g + (size_t)r * ldg + kc * 8);
    }
}
// 64 rows x 128 cols bf16 (256B rows), same swizzle (16 chunks/row).
__device__ __forceinline__ void load_tile_64x128(uint32_t sdst, const __nv_bfloat16* g, int ldg) {
    const int tid = threadIdx.x;
    #pragma unroll
    for (int i = 0; i < 4; i++) {
        const int c = tid + i * 256;
        const int r = c >> 4, kc = c & 15;
        const uint32_t so = sdst + r * 256 + (((uint32_t)kc * 16) ^ ((r & 7) * 16));
        cp16(so, g + (size_t)r * ldg + kc * 8);
    }
}

// acc += A(128x64, row-major-in-smem 128B rows) * B(128x64)^T, warp (wm 0-1, wn 0-3)
__device__ __forceinline__ void compute_chunk(uint32_t sA, uint32_t sB,
                                              int wm, int wn, int lane,
                                              float acc[4][4][4]) {
    #pragma unroll
    for (int ks = 0; ks < 4; ks++) {
        const int kc = ks * 2 + (lane >> 4);
        uint32_t a[4][4];
        #pragma unroll
        for (int mi = 0; mi < 4; mi++) {
            const int row = wm * 64 + mi * 16 + (lane & 15);
            ldsm4(a[mi], sA + row * 128 + (((uint32_t)kc * 16) ^ ((row & 7) * 16)));
        }
        uint32_t b[4][2];
        #pragma unroll
        for (int nh = 0; nh < 2; nh++) {
            const int row = wn * 32 + nh * 16 + (lane & 15);
            uint32_t r4[4];
            ldsm4(r4, sB + row * 128 + (((uint32_t)kc * 16) ^ ((row & 7) * 16)));
            b[nh * 2 + 0][0] = r4[0]; b[nh * 2 + 0][1] = r4[2];
            b[nh * 2 + 1][0] = r4[1]; b[nh * 2 + 1][1] = r4[3];
        }
        #pragma unroll
        for (int mi = 0; mi < 4; mi++)
            #pragma unroll
            for (int ni = 0; ni < 4; ni++)
                mma16816(acc[mi][ni], a[mi], b[ni][0], b[ni][1]);
    }
}

// acc += At(64x128 smem tile, [k][m] layout 256B rows) ^T * B(128x64)^T
// A fragments via ldmatrix.trans.
__device__ __forceinline__ void compute_chunk_At(uint32_t sA, uint32_t sB,
                                                 int wm, int wn, int lane,
                                                 float acc[4][4][4]) {
    #pragma unroll
    for (int ks = 0; ks < 4; ks++) {
        uint32_t a[4][4];
        const int crow_l = ks * 16 + (lane & 7) + ((lane >> 4) & 1) * 8;
        #pragma unroll
        for (int mi = 0; mi < 4; mi++) {
            const int scol = wm * 64 + mi * 16 + ((lane >> 3) & 1) * 8;
            ldsm4t(a[mi], sA + crow_l * 256 + ((((uint32_t)scol >> 3) * 16) ^ ((crow_l & 7) * 16)));
        }
        const int kc = ks * 2 + (lane >> 4);
        uint32_t b[4][2];
        #pragma unroll
        for (int nh = 0; nh < 2; nh++) {
            const int row = wn * 32 + nh * 16 + (lane & 15);
            uint32_t r4[4];
            ldsm4(r4, sB + row * 128 + (((uint32_t)kc * 16) ^ ((row & 7) * 16)));
            b[nh * 2 + 0][0] = r4[0]; b[nh * 2 + 0][1] = r4[2];
            b[nh * 2 + 1][0] = r4[1]; b[nh * 2 + 1][1] = r4[3];
        }
        #pragma unroll
        for (int mi = 0; mi < 4; mi++)
            #pragma unroll
            for (int ni = 0; ni < 4; ni++)
                mma16816(acc[mi][ni], a[mi], b[ni][0], b[ni][1]);
    }
}

#define ZERO_ACC(acc) do { \
    _Pragma("unroll") for (int _a = 0; _a < 4; _a++) \
    _Pragma("unroll") for (int _b = 0; _b < 4; _b++) \
    _Pragma("unroll") for (int _c = 0; _c < 4; _c++) acc[_a][_b][_c] = 0.0f; } while (0)

// ============================ prep: bf16 conversions + Z zero ============================
__global__ __launch_bounds__(256) void prep_bf16(const float4* __restrict__ x,
                                                 const float4* __restrict__ theta_w,
                                                 const float4* __restrict__ phi_w,
                                                 const float4* __restrict__ proj_w,
                                                 uint2* __restrict__ xb,
                                                 uint2* __restrict__ w2,
                                                 uint2* __restrict__ w3,
                                                 float* __restrict__ Z, int n4)
{
    const int gt = blockIdx.x * blockDim.x + threadIdx.x;
    const int stride = gridDim.x * blockDim.x;
    if (gt < NBATCH * SDIM) Z[gt] = 0.0f;
    for (int i = gt; i < n4; i += stride) {
        float4 v = x[i];
        __nv_bfloat162 a = __floats2bfloat162_rn(v.x, v.y);
        __nv_bfloat162 b = __floats2bfloat162_rn(v.z, v.w);
        xb[i] = make_uint2(*reinterpret_cast<uint32_t*>(&a), *reinterpret_cast<uint32_t*>(&b));
    }
    if (gt < 8192) {        // theta_w 128x256 = 32768 elems
        float4 v = theta_w[gt];
        __nv_bfloat162 a = __floats2bfloat162_rn(v.x, v.y);
        __nv_bfloat162 b = __floats2bfloat162_rn(v.z, v.w);
        w2[gt] = make_uint2(*reinterpret_cast<uint32_t*>(&a), *reinterpret_cast<uint32_t*>(&b));
        v = phi_w[gt];
        a = __floats2bfloat162_rn(v.x, v.y);
        b = __floats2bfloat162_rn(v.z, v.w);
        w2[8192 + gt] = make_uint2(*reinterpret_cast<uint32_t*>(&a), *reinterpret_cast<uint32_t*>(&b));
    }
    if (gt < 16384) {       // proj_w 256x256
        float4 v = proj_w[gt];
        __nv_bfloat162 a = __floats2bfloat162_rn(v.x, v.y);
        __nv_bfloat162 b = __floats2bfloat162_rn(v.z, v.w);
        w3[gt] = make_uint2(*reinterpret_cast<uint32_t*>(&a), *reinterpret_cast<uint32_t*>(&b));
    }
}

// smem stage offsets
#define SA2(st) ((uint32_t)((st) * 32768))
#define SB2(st) ((uint32_t)((st) * 32768 + 16384))

// ============================ theta/phi projection (HMMA, trans-A) ============================
// tp[n][s][o] = sum_c xb[n][c][s] * w2[o][c].  grid (2 o-tiles, 32 s-tiles, 4), 256 thr, K=256.
__global__ __launch_bounds__(256)
void thetaphi_hmma(const __nv_bfloat16* __restrict__ xb,
                   const __nv_bfloat16* __restrict__ w2,
                   __nv_bfloat16* __restrict__ tp)
{
    extern __shared__ char smem[];
    const uint32_t sb = smem_u32(smem);
    const int tid = threadIdx.x, lane = tid & 31, wid = tid >> 5;
    const int wm = wid & 1, wn = wid >> 1;
    const int z = blockIdx.z, m0 = blockIdx.y * 128, n0 = blockIdx.x * 128;

    const __nv_bfloat16* Abase = xb + (size_t)z * CDIM * SDIM + m0; // row c stride SDIM, col s
    const __nv_bfloat16* Bbase = w2 + (size_t)n0 * 256;

    float acc[4][4][4];
    ZERO_ACC(acc);

    load_tile_64x128(sb + SA2(0), Abase, SDIM);
    load_tile_128x64(sb + SB2(0), Bbase, 256);
    CP_COMMIT();

    const int KT = 4;
    #pragma unroll
    for (int kt = 0; kt < KT; kt++) {
        if (kt + 1 < KT) {
            load_tile_64x128(sb + SA2((kt + 1) & 1), Abase + (size_t)(kt + 1) * 64 * SDIM, SDIM);
            load_tile_128x64(sb + SB2((kt + 1) & 1), Bbase + (kt + 1) * 64, 256);
            CP_COMMIT();
            CP_WAIT(1);
        } else {
            CP_WAIT(0);
        }
        __syncthreads();
        compute_chunk_At(sb + SA2(kt & 1), sb + SB2(kt & 1), wm, wn, lane, acc);
        __syncthreads();
    }

    const int lrow = lane >> 2, lcol2 = (lane & 3) * 2;
    #pragma unroll
    for (int mi = 0; mi < 4; mi++) {
        const int gr0 = m0 + wm * 64 + mi * 16 + lrow;
        #pragma unroll
        for (int ni = 0; ni < 4; ni++) {
            const int col = n0 + wn * 32 + ni * 8 + lcol2;
            __nv_bfloat162 h0 = __floats2bfloat162_rn(acc[mi][ni][0], acc[mi][ni][1]);
            __nv_bfloat162 h1 = __floats2bfloat162_rn(acc[mi][ni][2], acc[mi][ni][3]);
            *reinterpret_cast<uint32_t*>(tp + ((size_t)z * SDIM + gr0) * 256 + col) =
                *reinterpret_cast<uint32_t*>(&h0);
            *reinterpret_cast<uint32_t*>(tp + ((size_t)z * SDIM + gr0 + 8) * 256 + col) =
                *reinterpret_cast<uint32_t*>(&h1);
        }
    }
}

// ============================ fused logits + exp (HMMA) ============================
__global__ __launch_bounds__(256)
void logits_exp_hmma(const __nv_bfloat16* __restrict__ tp,
                     __nv_bfloat16* __restrict__ f,
                     float* __restrict__ Z)
{
    extern __shared__ char smem[];
    const uint32_t sb = smem_u32(smem);
    const int tid = threadIdx.x, lane = tid & 31, wid = tid >> 5;
    const int wm = wid & 1, wn = wid >> 1;
    const int z = blockIdx.z, m0 = blockIdx.y * 128, n0 = blockIdx.x * 128;

    const __nv_bfloat16* Abase = tp + ((size_t)(z * SDIM + m0)) * 256;        // theta
    const __nv_bfloat16* Bbase = tp + ((size_t)(z * SDIM + n0)) * 256 + 128;  // phi

    float acc[4][4][4];
    ZERO_ACC(acc);

    load_tile_128x64(sb + SA2(0), Abase, 256);
    load_tile_128x64(sb + SB2(0), Bbase, 256);
    CP_COMMIT();
    load_tile_128x64(sb + SA2(1), Abase + 64, 256);
    load_tile_128x64(sb + SB2(1), Bbase + 64, 256);
    CP_COMMIT();

    CP_WAIT(1);
    __syncthreads();
    compute_chunk(sb + SA2(0), sb + SB2(0), wm, wn, lane, acc);
    CP_WAIT(0);
    __syncthreads();
    compute_chunk(sb + SA2(1), sb + SB2(1), wm, wn, lane, acc);

    const float alpha = 0.08838834764831845f; // 1/sqrt(128)
    const int lrow = lane >> 2, lcol2 = (lane & 3) * 2;
    #pragma unroll
    for (int mi = 0; mi < 4; mi++) {
        const int gr0 = m0 + wm * 64 + mi * 16 + lrow;
        const int gr1 = gr0 + 8;
        float rs0 = 0.0f, rs1 = 0.0f;
        #pragma unroll
        for (int ni = 0; ni < 4; ni++) {
            const int col = n0 + wn * 32 + ni * 8 + lcol2;
            float e00 = __expf(acc[mi][ni][0] * alpha);
            float e01 = __expf(acc[mi][ni][1] * alpha);
            float e10 = __expf(acc[mi][ni][2] * alpha);
            float e11 = __expf(acc[mi][ni][3] * alpha);
            rs0 += e00 + e01; rs1 += e10 + e11;
            __nv_bfloat162 h0 = __floats2bfloat162_rn(e00, e01);
            __nv_bfloat162 h1 = __floats2bfloat162_rn(e10, e11);
            *reinterpret_cast<uint32_t*>(f + ((size_t)z * SDIM + gr0) * SDIM + col) =
                *reinterpret_cast<uint32_t*>(&h0);
            *reinterpret_cast<uint32_t*>(f + ((size_t)z * SDIM + gr1) * SDIM + col) =
                *reinterpret_cast<uint32_t*>(&h1);
        }
        rs0 += __shfl_xor_sync(0xffffffffu, rs0, 1);
        rs0 += __shfl_xor_sync(0xffffffffu, rs0, 2);
        rs1 += __shfl_xor_sync(0xffffffffu, rs1, 1);
        rs1 += __shfl_xor_sync(0xffffffffu, rs1, 2);
        if ((lane & 3) == 0) {
            atomicAdd(&Z[(size_t)z * SDIM + gr0], rs0);
            atomicAdd(&Z[(size_t)z * SDIM + gr1], rs1);
        }
    }
}

// ============================ attend (HMMA, 3-stage): y = (f @ x^T)/Z, bf16 out ============================
#define SA3(st) ((uint32_t)((st) * 32768))
#define SB3(st) ((uint32_t)((st) * 32768 + 16384))
__global__ __launch_bounds__(256)
void attend_hmma(const __nv_bfloat16* __restrict__ f,
                 const __nv_bfloat16* __restrict__ xb,
                 const float* __restrict__ Z,
                 __nv_bfloat16* __restrict__ y)
{
    extern __shared__ char smem[];
    const uint32_t sb = smem_u32(smem);
    const int tid = threadIdx.x, lane = tid & 31, wid = tid >> 5;
    const int wm = wid & 1, wn = wid >> 1;
    const int z = blockIdx.z, m0 = blockIdx.y * 128, n0 = blockIdx.x * 128;

    const __nv_bfloat16* Abase = f + ((size_t)z * SDIM + m0) * SDIM;
    const __nv_bfloat16* Bbase = xb + ((size_t)z * CDIM + n0) * SDIM;

    float acc[4][4][4];
    ZERO_ACC(acc);

    load_tile_128x64(sb + SA3(0), Abase, SDIM);
    load_tile_128x64(sb + SB3(0), Bbase, SDIM);
    CP_COMMIT();
    load_tile_128x64(sb + SA3(1), Abase + 64, SDIM);
    load_tile_128x64(sb + SB3(1), Bbase + 64, SDIM);
    CP_COMMIT();

    const int KT = SDIM / 64; // 64
    for (int kt = 0; kt < KT; kt++) {
        if (kt + 1 < KT) { CP_WAIT(1); } else { CP_WAIT(0); }
        __syncthreads();
        if (kt + 2 < KT) {
            const int st = (kt + 2) % 3;
            load_tile_128x64(sb + SA3(st), Abase + (kt + 2) * 64, SDIM);
            load_tile_128x64(sb + SB3(st), Bbase + (kt + 2) * 64, SDIM);
            CP_COMMIT();
        }
        compute_chunk(sb + SA3(kt % 3), sb + SB3(kt % 3), wm, wn, lane, acc);
    }

    const int lrow = lane >> 2, lcol2 = (lane & 3) * 2;
    #pragma unroll
    for (int mi = 0; mi < 4; mi++) {
        const int gr0 = m0 + wm * 64 + mi * 16 + lrow;
        const int gr1 = gr0 + 8;
        const float iz0 = 1.0f / Z[(size_t)z * SDIM + gr0];
        const float iz1 = 1.0f / Z[(size_t)z * SDIM + gr1];
        #pragma unroll
        for (int ni = 0; ni < 4; ni++) {
            const int col = n0 + wn * 32 + ni * 8 + lcol2;
            __nv_bfloat162 h0 = __floats2bfloat162_rn(acc[mi][ni][0] * iz0, acc[mi][ni][1] * iz0);
            __nv_bfloat162 h1 = __floats2bfloat162_rn(acc[mi][ni][2] * iz1, acc[mi][ni][3] * iz1);
            *reinterpret_cast<uint32_t*>(y + ((size_t)z * SDIM + gr0) * CDIM + col) =
                *reinterpret_cast<uint32_t*>(&h0);
            *reinterpret_cast<uint32_t*>(y + ((size_t)z * SDIM + gr1) * CDIM + col) =
                *reinterpret_cast<uint32_t*>(&h1);
        }
    }
}

// ============================ projection + residual (HMMA) ============================
// out[n][o][s] = x[n][o][s] + sum_c w3[o,c] * y[n][s][c].  grid (32 s-tiles, 2 o-tiles, 4).
__global__ __launch_bounds__(256)
void proj_hmma(const __nv_bfloat16* __restrict__ w3,
               const __nv_bfloat16* __restrict__ y,
               const float* __restrict__ x,
               float* __restrict__ out)
{
    extern __shared__ char smem[];
    const uint32_t sb = smem_u32(smem);
    const int tid = threadIdx.x, lane = tid & 31, wid = tid >> 5;
    const int wm = wid & 1, wn = wid >> 1;
    const int z = blockIdx.z, m0 = blockIdx.y * 128, n0 = blockIdx.x * 128;

    const __nv_bfloat16* Abase = w3 + (size_t)m0 * 256;
    const __nv_bfloat16* Bbase = y + ((size_t)z * SDIM + n0) * CDIM;

    float acc[4][4][4];
    ZERO_ACC(acc);

    load_tile_128x64(sb + SA2(0), Abase, 256);
    load_tile_128x64(sb + SB2(0), Bbase, 256);
    CP_COMMIT();

    const int KT = 4;
    #pragma unroll
    for (int kt = 0; kt < KT; kt++) {
        if (kt + 1 < KT) {
            load_tile_128x64(sb + SA2((kt + 1) & 1), Abase + (kt + 1) * 64, 256);
            load_tile_128x64(sb + SB2((kt + 1) & 1), Bbase + (kt + 1) * 64, 256);
            CP_COMMIT();
            CP_WAIT(1);
        } else {
            CP_WAIT(0);
        }
        __syncthreads();
        compute_chunk(sb + SA2(kt & 1), sb + SB2(kt & 1), wm, wn, lane, acc);
        __syncthreads();
    }

    const int lrow = lane >> 2, lcol2 = (lane & 3) * 2;
    #pragma unroll
    for (int mi = 0; mi < 4; mi++) {
        const int gr0 = m0 + wm * 64 + mi * 16 + lrow;  // o
        const int gr1 = gr0 + 8;
        #pragma unroll
        for (int ni = 0; ni < 4; ni++) {
            const int col = n0 + wn * 32 + ni * 8 + lcol2;  // s
            const float2 x0 = *reinterpret_cast<const float2*>(x + ((size_t)z * CDIM + gr0) * SDIM + col);
            const float2 x1 = *reinterpret_cast<const float2*>(x + ((size_t)z * CDIM + gr1) * SDIM + col);
            float2 v0 = make_float2(acc[mi][ni][0] + x0.x, acc[mi][ni][1] + x0.y);
            float2 v1 = make_float2(acc[mi][ni][2] + x1.x, acc[mi][ni][3] + x1.y);
            *reinterpret_cast<float2*>(out + ((size_t)z * CDIM + gr0) * SDIM + col) = v0;
            *reinterpret_cast<float2*>(out + ((size_t)z * CDIM + gr1) * SDIM + col) = v1;
        }
    }
}

// ============================ launch ============================
extern "C" void kernel_launch(void* const* d_in, const int* in_sizes, int n_in,
                              void* d_out, int out_size)
{
    const float* x       = (const float*)d_in[0];
    const float* theta_w = (const float*)d_in[1];
    const float* phi_w   = (const float*)d_in[2];
    const float* proj_w  = (const float*)d_in[3];
    float* out = (float*)d_out;

    __nv_bfloat16 *tp, *f, *xb, *yb, *w2, *w3;
    float *Z;
    cudaGetSymbolAddress((void**)&tp, g_tp);
    cudaGetSymbolAddress((void**)&f,  g_f);
    cudaGetSymbolAddress((void**)&xb, g_xb);
    cudaGetSymbolAddress((void**)&yb, g_yb);
    cudaGetSymbolAddress((void**)&w2, g_w2);
    cudaGetSymbolAddress((void**)&w3, g_w3);
    cudaGetSymbolAddress((void**)&Z,  g_Z);

    cudaFuncSetAttribute(thetaphi_hmma,   cudaFuncAttributeMaxDynamicSharedMemorySize, 65536);
    cudaFuncSetAttribute(logits_exp_hmma, cudaFuncAttributeMaxDynamicSharedMemorySize, 65536);
    cudaFuncSetAttribute(attend_hmma,     cudaFuncAttributeMaxDynamicSharedMemorySize, 98304);
    cudaFuncSetAttribute(proj_hmma,       cudaFuncAttributeMaxDynamicSharedMemorySize, 65536);

    // 0: bf16 conversions + Z zero
    prep_bf16<<<1024, 256>>>((const float4*)x, (const float4*)theta_w, (const float4*)phi_w,
                             (const float4*)proj_w, (uint2*)xb, (uint2*)w2, (uint2*)w3, Z,
                             (int)((size_t)NBATCH * CDIM * SDIM / 4));

    // 1: fused theta+phi projection [HMMA trans-A]
    thetaphi_hmma<<<dim3(2, 32, 4), 256, 65536>>>(xb, w2, tp);

    // 2: fused logits -> exp + row sums [HMMA]
    logits_exp_hmma<<<dim3(32, 32, 4), 256, 65536>>>(tp, f, Z);

    // 3: attend + 1/Z, bf16 out [HMMA 3-stage]
    attend_hmma<<<dim3(2, 32, 4), 256, 98304>>>(f, xb, Z, yb);

    // 4: projection + residual [HMMA]
    proj_hmma<<<dim3(32, 2, 4), 256, 65536>>>(w3, yb, x, out);
}